// round 16
// baseline (speedup 1.0000x reference)
#include <cuda_runtime.h>
#include <cstdint>

// Problem dims
#define TT 128
#define BB 256
#define II 512
#define HH 1024
#define VV 128
#define OO 64
#define NG 4096   // 4*H

// Decomposition (champion shape)
#define NCTA 128        // 2 batch-blocks x 64 unit-blocks
#define BT 128          // batch rows per CTA (M)
#define UT 16           // hidden units per CTA
#define CT 64           // gate cols per CTA (N)
#define KC 64           // K chunk
#define NKC (HH/KC)     // 16
#define NTHR 256        // 8 warps: 4x2 warp grid, 32x32 tile per warp

#define AS_STRIDE 68
#define STAGE_FLOATS ((BT + CT) * AS_STRIDE)   // 13056

// smem float offsets: tokens + 4 pipeline stages (P table in global scratch)
#define OFF_TOK 0                         // 136 ints
#define OFF_B0  136
#define SMEM_FLOATS (OFF_B0 + 4*STAGE_FLOATS)   // 209440 B

// ---- static scratch ----
__device__ float g_h[2*BB*HH];        // ping-pong hidden state (tf32; fp32 last step)
__device__ float g_w[NG*HH];          // tf32-pre-rounded w_hh
__device__ float g_p[NCTA*VV*CT];     // 4 MB P table: per-CTA slice [128 vocab x 64 cols]
__device__ unsigned g_cnt;            // global init barrier
__device__ unsigned g_rel;
__device__ unsigned g_cnt2[2];        // per-batch-half barriers (64 CTAs each)
__device__ unsigned g_rel2[2];

__device__ __forceinline__ float tf32r(float x) {
    unsigned v; asm("cvt.rna.tf32.f32 %0, %1;" : "=r"(v) : "f"(x));
    return __uint_as_float(v);
}
__device__ __forceinline__ unsigned ld_acq(const unsigned* p) {
    unsigned v; asm volatile("ld.acquire.gpu.u32 %0, [%1];" : "=r"(v) : "l"(p) : "memory");
    return v;
}
// Global barrier (init only)
__device__ __forceinline__ void grid_sync() {
    __syncthreads();
    if (threadIdx.x == 0) {
        unsigned r0 = ld_acq(&g_rel);
        __threadfence();
        unsigned old = atomicAdd(&g_cnt, 1u);
        if (old == (unsigned)(NCTA - 1)) {
            g_cnt = 0; __threadfence(); atomicAdd(&g_rel, 1u);
        } else {
            while (ld_acq(&g_rel) == r0) { }
        }
    }
    __syncthreads();
}
// Half barrier: 64 CTAs of one batch block (the two halves are data-independent)
__device__ __forceinline__ void half_sync(int hb) {
    __syncthreads();
    if (threadIdx.x == 0) {
        unsigned r0 = ld_acq(&g_rel2[hb]);
        __threadfence();
        unsigned old = atomicAdd(&g_cnt2[hb], 1u);
        if (old == 63u) {
            g_cnt2[hb] = 0; __threadfence(); atomicAdd(&g_rel2[hb], 1u);
        } else {
            while (ld_acq(&g_rel2[hb]) == r0) { }
        }
    }
    __syncthreads();
}

// col j -> gate=(j>>3)&3, unit=(j>>5)*8+(j&7): all 4 gates of a cell in one thread.
__device__ __forceinline__ int colIdx(int j, int unit0) {
    return (((j >> 3) & 3) << 10) + unit0 + ((j >> 5) << 3) + (j & 7);
}

__device__ __forceinline__ void mma8(float d[4], const unsigned a[4],
                                     unsigned b0, unsigned b1) {
    asm volatile(
        "mma.sync.aligned.m16n8k8.row.col.f32.tf32.tf32.f32 "
        "{%0,%1,%2,%3}, {%4,%5,%6,%7}, {%8,%9}, {%0,%1,%2,%3};\n"
        : "+f"(d[0]), "+f"(d[1]), "+f"(d[2]), "+f"(d[3])
        : "r"(a[0]), "r"(a[1]), "r"(a[2]), "r"(a[3]), "r"(b0), "r"(b1));
}
__device__ __forceinline__ void ldsm4(unsigned addr, unsigned& r0, unsigned& r1,
                                      unsigned& r2, unsigned& r3) {
    asm volatile("ldmatrix.sync.aligned.m8n8.x4.shared.b16 {%0,%1,%2,%3}, [%4];"
                 : "=r"(r0), "=r"(r1), "=r"(r2), "=r"(r3) : "r"(addr));
}
__device__ __forceinline__ void cpa16(unsigned dst, const float* src) {
    asm volatile("cp.async.cg.shared.global [%0], [%1], 16;" :: "r"(dst), "l"(src));
}
#define CP_COMMIT() asm volatile("cp.async.commit_group;" ::: "memory")
template<int N> __device__ __forceinline__ void cp_wait() {
    asm volatile("cp.async.wait_group %0;" :: "n"(N) : "memory");
}

// fast pointwise ops
__device__ __forceinline__ float fsig(float x) {
    return __fdividef(1.0f, 1.0f + __expf(-x));
}
__device__ __forceinline__ float ftanh(float x) {
    return 1.0f - 2.0f * __fdividef(1.0f, __expf(2.0f * x) + 1.0f);
}

// Synchronous tile load with tf32 rounding (P-table phase only).
__device__ __forceinline__ void load_tiles_cvt(
    float* As, float* Ws,
    const float* __restrict__ A, int lda,
    const float* __restrict__ W, int ldw,
    int kc, int unit0, int tid)
{
#pragma unroll
    for (int i = 0; i < 8; i++) {
        int id = tid + NTHR * i;
        int r = id >> 4, q = id & 15;
        float4 v = __ldcg((const float4*)(A + (size_t)r * lda + kc + q * 4));
        v.x = tf32r(v.x); v.y = tf32r(v.y); v.z = tf32r(v.z); v.w = tf32r(v.w);
        *(float4*)(As + r * AS_STRIDE + q * 4) = v;
    }
#pragma unroll
    for (int i = 0; i < 4; i++) {
        int id = tid + NTHR * i;
        int r = id >> 4, q = id & 15;
        float4 v = __ldcg((const float4*)(W + (size_t)colIdx(r, unit0) * ldw + kc + q * 4));
        v.x = tf32r(v.x); v.y = tf32r(v.y); v.z = tf32r(v.z); v.w = tf32r(v.w);
        *(float4*)(Ws + r * AS_STRIDE + q * 4) = v;
    }
}

// ldmatrix-based chunk MMA: 2 A x4 fragments, 2 B x4 fragments.
__device__ __forceinline__ void mma_chunk(
    unsigned stg, const unsigned a_lm[2], const unsigned b_lm[2],
    float acc[2][4][4])
{
#pragma unroll
    for (int kk = 0; kk < KC; kk += 8) {
        unsigned a[2][4], b[2][4];
        ldsm4(stg + a_lm[0] + kk * 4, a[0][0], a[0][1], a[0][2], a[0][3]);
        ldsm4(stg + a_lm[1] + kk * 4, a[1][0], a[1][1], a[1][2], a[1][3]);
        ldsm4(stg + b_lm[0] + kk * 4, b[0][0], b[0][1], b[0][2], b[0][3]);
        ldsm4(stg + b_lm[1] + kk * 4, b[1][0], b[1][1], b[1][2], b[1][3]);
#pragma unroll
        for (int mb = 0; mb < 2; mb++) {
            mma8(acc[mb][0], a[mb], b[0][0], b[0][1]);
            mma8(acc[mb][1], a[mb], b[0][2], b[0][3]);
            mma8(acc[mb][2], a[mb], b[1][0], b[1][1]);
            mma8(acc[mb][3], a[mb], b[1][2], b[1][3]);
        }
    }
}

__global__ void __launch_bounds__(NTHR, 1)
lstm_persistent_kernel(
    const void* __restrict__ inp_raw,
    const float* __restrict__ h0,
    const float* __restrict__ c0,
    const float* __restrict__ emb,
    const float* __restrict__ w_ih,
    const float* __restrict__ w_hh,
    const float* __restrict__ b_ih,
    const float* __restrict__ b_hh,
    const float* __restrict__ w_out,
    const float* __restrict__ b_out,
    float* __restrict__ out)
{
    extern __shared__ float sm[];
    int* toksm = (int*)(sm + OFF_TOK);

    const int tid  = threadIdx.x;
    const int lane = tid & 31, wid = tid >> 5;
    const int warp_m = wid >> 1, warp_n = wid & 1;  // 4x2
    const int cid = blockIdx.x;
    const int bi = cid >> 6, hi = cid & 63;
    const int b0 = bi * BT;
    const int unit0 = hi * UT;
    const int lg = lane >> 2, lt = lane & 3;

    const unsigned sbase = (unsigned)__cvta_generic_to_shared(sm);
    const int* inp32 = (const int*)inp_raw;
    const long long* inp64 = (const long long*)inp_raw;
    float* Pcta = g_p + (size_t)cid * (VV * CT);     // this CTA's P slice

    // ---- token dtype detection ----
    if (tid == 0) toksm[128] = 0;
    __syncthreads();
    {
        int f = 0;
        for (int i = tid; i < 128; i += NTHR)
            if (inp32[2 * i + 1] != 0) f = 1;
        if (f) atomicOr(&toksm[128], 1);
    }

    // ---- init: tf32-round w_hh -> g_w; tf32-round h0 -> g_h buf0 ----
    {
        const float4* src = (const float4*)w_hh;
        float4* dst = (float4*)g_w;
        int base = cid * ((NG * HH / 4) / NCTA);
        for (int i = tid; i < (NG * HH / 4) / NCTA; i += NTHR) {
            float4 v = src[base + i];
            v.x = tf32r(v.x); v.y = tf32r(v.y); v.z = tf32r(v.z); v.w = tf32r(v.w);
            dst[base + i] = v;
        }
        const float4* hs = (const float4*)h0;
        float4* hd = (float4*)g_h;
        int hb = cid * ((BB * HH / 4) / NCTA);
        for (int i = tid; i < (BB * HH / 4) / NCTA; i += NTHR) {
            float4 v = hs[hb + i];
            v.x = tf32r(v.x); v.y = tf32r(v.y); v.z = tf32r(v.z); v.w = tf32r(v.w);
            hd[hb + i] = v;
        }
    }

    // ---- c state in registers ----
    float creg[8];
    {
        const int u0 = unit0 + warp_n * 8 + (lt << 1);
#pragma unroll
        for (int mb = 0; mb < 2; mb++)
#pragma unroll
            for (int rh = 0; rh < 2; rh++) {
                int r = warp_m * 32 + mb * 16 + rh * 8 + lg;
                const float2 cv = *(const float2*)(c0 + (size_t)(b0 + r) * HH + u0);
                creg[mb * 4 + rh * 2 + 0] = cv.x;
                creg[mb * 4 + rh * 2 + 1] = cv.y;
            }
    }
    grid_sync();                       // global: init is striped across all CTAs
    const int tok_is_32 = toksm[128];

    // ---- per-thread cp.async address precompute ----
    int a_src[8];  unsigned a_dst[8];
    int w_src[4];  unsigned w_dst[4];
#pragma unroll
    for (int i = 0; i < 8; i++) {
        int id = tid + NTHR * i;
        int r = id >> 4, q = id & 15;
        a_src[i] = r * HH + q * 4;
        a_dst[i] = (unsigned)((r * AS_STRIDE + q * 4) * 4);
    }
#pragma unroll
    for (int i = 0; i < 4; i++) {
        int id = tid + NTHR * i;
        int r = id >> 4, q = id & 15;
        w_src[i] = colIdx(r, unit0) * HH + q * 4;
        w_dst[i] = (unsigned)(((BT * AS_STRIDE) + r * AS_STRIDE + q * 4) * 4);
    }
    unsigned bufb[4];
#pragma unroll
    for (int s = 0; s < 4; s++) bufb[s] = sbase + (OFF_B0 + s * STAGE_FLOATS) * 4;

    // ---- per-lane ldmatrix offsets ----
    unsigned a_lm[2], b_lm[2];
#pragma unroll
    for (int mb = 0; mb < 2; mb++) {
        int row = warp_m * 32 + mb * 16 + (lane & 7) + (((lane >> 3) & 1) << 3);
        int col = (lane >> 4) << 2;
        a_lm[mb] = (unsigned)((row * AS_STRIDE + col) * 4);
    }
#pragma unroll
    for (int p = 0; p < 2; p++) {
        int row = warp_n * 32 + p * 16 + (lane & 7) + ((lane >> 4) << 3);
        int col = ((lane >> 3) & 1) << 2;
        b_lm[p] = (unsigned)(((BT * AS_STRIDE) + row * AS_STRIDE + col) * 4);
    }

    // ---- P table -> g_p (global, per-CTA slice) ----
    {
        float* As = sm + OFF_B0;
        float* Ws = As + BT * AS_STRIDE;
        float acc[2][4][4];
#pragma unroll
        for (int mb = 0; mb < 2; mb++)
#pragma unroll
            for (int nb = 0; nb < 4; nb++)
#pragma unroll
                for (int e = 0; e < 4; e++) acc[mb][nb][e] = 0.f;

        for (int kc = 0; kc < II; kc += KC) {
            __syncthreads();
            load_tiles_cvt(As, Ws, emb, II, w_ih, II, kc, unit0, tid);
            __syncthreads();
            mma_chunk(bufb[0], a_lm, b_lm, acc);
        }
        __syncthreads();
#pragma unroll
        for (int mb = 0; mb < 2; mb++) {
            int r0 = warp_m * 32 + mb * 16 + lg;
#pragma unroll
            for (int nb = 0; nb < 4; nb++) {
                int c0c = warp_n * 32 + nb * 8 + (lt << 1);
                int gc0 = colIdx(c0c, unit0), gc1 = colIdx(c0c + 1, unit0);
                float bias0 = b_ih[gc0] + b_hh[gc0];
                float bias1 = b_ih[gc1] + b_hh[gc1];
                Pcta[r0 * CT + c0c]           = acc[mb][nb][0] + bias0;
                Pcta[r0 * CT + c0c + 1]       = acc[mb][nb][1] + bias1;
                Pcta[(r0 + 8) * CT + c0c]     = acc[mb][nb][2] + bias0;
                Pcta[(r0 + 8) * CT + c0c + 1] = acc[mb][nb][3] + bias1;
            }
        }
        __threadfence();
        __syncthreads();
    }

    // ---- issue W chunk 0 for step 0 (uncommitted; commits with A0) ----
#pragma unroll
    for (int i = 0; i < 4; i++) cpa16(bufb[0] + w_dst[i], g_w + w_src[i]);

    const int pc = warp_n * 32 + (lt << 1);   // base P col for gate 0
    const int u0 = unit0 + warp_n * 8 + (lt << 1);

    // ---- recurrence: 4-stage pipeline, chunk PAIRS, per-half barrier, P prefetch ----
    for (int t = 0; t < TT; t++) {
        const float* Ag = g_h + (size_t)(t & 1) * (BB * HH) + (size_t)b0 * HH;
        float* Hout = g_h + (size_t)((t + 1) & 1) * (BB * HH);

        if (tid < BT) {
            toksm[tid] = tok_is_32 ? inp32[t * BB + b0 + tid]
                                   : (int)inp64[(size_t)t * BB + b0 + tid];
        }

        float acc[2][4][4];
#pragma unroll
        for (int mb = 0; mb < 2; mb++)
#pragma unroll
            for (int nb = 0; nb < 4; nb++)
#pragma unroll
                for (int e = 0; e < 4; e++) acc[mb][nb][e] = 0.f;

        // chunk 0 (A) -> stage0, commit {W0,A0}; chunk 1 (A+W) -> stage1, commit
#pragma unroll
        for (int i = 0; i < 8; i++) cpa16(bufb[0] + a_dst[i], Ag + a_src[i]);
        CP_COMMIT();
#pragma unroll
        for (int i = 0; i < 8; i++) cpa16(bufb[1] + a_dst[i], Ag + a_src[i] + KC);
#pragma unroll
        for (int i = 0; i < 4; i++) cpa16(bufb[1] + w_dst[i], g_w + w_src[i] + KC);
        CP_COMMIT();

        float2 pf[2][2][4];   // prefetched P[token] rows, loaded at pair-iter 0

        // pair loop: wait(2i,2i+1) -> bar -> [i==0: P prefetch] -> issue(2i+2,2i+3) -> mma x2
#pragma unroll 1
        for (int i = 0; i < NKC / 2; i++) {
            cp_wait<0>();
            __syncthreads();
            if (i == 0) {
#pragma unroll
                for (int mb = 0; mb < 2; mb++) {
                    int r0 = warp_m * 32 + mb * 16 + lg;
                    int v0 = toksm[r0], v1 = toksm[r0 + 8];
#pragma unroll
                    for (int g = 0; g < 4; g++) {
                        pf[mb][0][g] = *(const float2*)(Pcta + v0 * CT + pc + g * 8);
                        pf[mb][1][g] = *(const float2*)(Pcta + v1 * CT + pc + g * 8);
                    }
                }
            }
            if (i < NKC / 2 - 1) {
                const int c2 = 2 * i + 2, c3 = 2 * i + 3;
                {
                    const int koff = c2 * KC;
                    const unsigned s_ = bufb[c2 & 3];
#pragma unroll
                    for (int j = 0; j < 8; j++) cpa16(s_ + a_dst[j], Ag + a_src[j] + koff);
#pragma unroll
                    for (int j = 0; j < 4; j++) cpa16(s_ + w_dst[j], g_w + w_src[j] + koff);
                    CP_COMMIT();
                }
                {
                    const int koff = c3 * KC;
                    const unsigned s_ = bufb[c3 & 3];
#pragma unroll
                    for (int j = 0; j < 8; j++) cpa16(s_ + a_dst[j], Ag + a_src[j] + koff);
#pragma unroll
                    for (int j = 0; j < 4; j++) cpa16(s_ + w_dst[j], g_w + w_src[j] + koff);
                    CP_COMMIT();
                }
            }
            mma_chunk(bufb[(2 * i) & 3], a_lm, b_lm, acc);
            mma_chunk(bufb[(2 * i + 1) & 3], a_lm, b_lm, acc);
        }

        // issue next step's W0 into stage0 (uncommitted; safe: stage0 last read mma(12),
        // every warp passed the pair-iter-7 barrier after that)
        const bool last = (t == TT - 1);
        if (!last) {
#pragma unroll
            for (int i = 0; i < 4; i++) cpa16(bufb[0] + w_dst[i], g_w + w_src[i]);
        }

        // ---- register epilogue (P already in registers) ----
        {
#pragma unroll
            for (int mb = 0; mb < 2; mb++) {
                int r0 = warp_m * 32 + mb * 16 + lg;
                float gv4[4][4];
#pragma unroll
                for (int g = 0; g < 4; g++) {
                    gv4[g][0] = acc[mb][g][0] + pf[mb][0][g].x;
                    gv4[g][1] = acc[mb][g][1] + pf[mb][0][g].y;
                    gv4[g][2] = acc[mb][g][2] + pf[mb][1][g].x;
                    gv4[g][3] = acc[mb][g][3] + pf[mb][1][g].y;
                }
#pragma unroll
                for (int rh = 0; rh < 2; rh++) {
                    float hv[2];
#pragma unroll
                    for (int e = 0; e < 2; e++) {
                        int ix = rh * 2 + e;
                        float iv = fsig(gv4[0][ix]);
                        float fv = fsig(gv4[1][ix]);
                        float gg = ftanh(gv4[2][ix]);
                        float ov = fsig(gv4[3][ix]);
                        float cn = fv * creg[mb * 4 + ix] + iv * gg;
                        float hn = ov * ftanh(cn);
                        creg[mb * 4 + ix] = cn;
                        hv[e] = last ? hn : tf32r(hn);
                    }
                    int r = r0 + rh * 8;
                    *(float2*)(Hout + (size_t)(b0 + r) * HH + u0) = make_float2(hv[0], hv[1]);
                }
            }
        }
        half_sync(bi);      // the two batch halves are fully independent
    }

    // ---- output head: h_last (fp32) in buffer 0; rows belong to this CTA's half ----
    if (tid < 128) {
        int id = cid * 128 + tid;
        int b = id >> 6, o = id & 63;
        const float4* hr = (const float4*)(g_h + (size_t)b * HH);
        const float4* wr = (const float4*)(w_out + (size_t)o * HH);
        float s = 0.f;
#pragma unroll 8
        for (int k = 0; k < HH / 4; k++) {
            float4 a = __ldcg(hr + k);
            float4 w = wr[k];
            s += a.x * w.x + a.y * w.y + a.z * w.z + a.w * w.w;
        }
        out[id] = s + b_out[o];
    }
}

extern "C" void kernel_launch(void* const* d_in, const int* in_sizes, int n_in,
                              void* d_out, int out_size) {
    (void)in_sizes; (void)n_in; (void)out_size;
    const size_t smem_bytes = (size_t)SMEM_FLOATS * sizeof(float);
    cudaFuncSetAttribute(lstm_persistent_kernel,
                         cudaFuncAttributeMaxDynamicSharedMemorySize, (int)smem_bytes);
    lstm_persistent_kernel<<<NCTA, NTHR, smem_bytes>>>(
        (const void*)d_in[0],
        (const float*)d_in[1],
        (const float*)d_in[2],
        (const float*)d_in[3],
        (const float*)d_in[4],
        (const float*)d_in[5],
        (const float*)d_in[6],
        (const float*)d_in[7],
        (const float*)d_in[8],
        (const float*)d_in[9],
        (float*)d_out);
}